// round 3
// baseline (speedup 1.0000x reference)
#include <cuda_runtime.h>

#define Bq 4
#define Sq 2048
#define Eq 1024
#define Hq 16

typedef unsigned long long u64t;

// ---------------- scratch (device globals; no allocs allowed) ----------------
__device__ float g_Q[Bq*Hq*Sq*64];          // [B,H,S,64]
__device__ float g_K[Bq*Hq*Sq*64];
__device__ float g_V[Bq*Hq*Sq*64];
__device__ float g_ctx[(size_t)Bq*Sq*Eq];   // [B*S, H*DV] merged heads
__device__ float g_proj[(size_t)Bq*Sq*Eq];  // context @ W_O
__device__ float g_rowmax[Bq*Hq*Sq];
__device__ float g_rinv[Bq*Hq*Sq];

extern __shared__ float smbuf[];

// ---------------- f32x2 packed-FMA helpers ----------------
__device__ __forceinline__ u64t pk2(float v) {
    u64t r; asm("mov.b64 %0, {%1,%1};" : "=l"(r) : "f"(v)); return r;
}
__device__ __forceinline__ void fma2(u64t& d, u64t a, u64t b) {
    asm("fma.rn.f32x2 %0, %1, %2, %0;" : "+l"(d) : "l"(a), "l"(b));
}
__device__ __forceinline__ float2 upk2(u64t v) {
    float2 f; asm("mov.b64 {%0,%1}, %2;" : "=f"(f.x), "=f"(f.y) : "l"(v)); return f;
}

// ---------------- block reductions ----------------
__device__ __forceinline__ float block_sum(float v) {
    __shared__ float sh[33];
    int lane = threadIdx.x & 31, w = threadIdx.x >> 5;
    #pragma unroll
    for (int o = 16; o; o >>= 1) v += __shfl_xor_sync(0xffffffffu, v, o);
    __syncthreads();
    if (lane == 0) sh[w] = v;
    __syncthreads();
    if (w == 0) {
        float x = (lane < 8) ? sh[lane] : 0.0f;
        #pragma unroll
        for (int o = 4; o; o >>= 1) x += __shfl_xor_sync(0xffffffffu, x, o);
        if (lane == 0) sh[32] = x;
    }
    __syncthreads();
    return sh[32];
}

__device__ __forceinline__ float block_max(float v) {
    __shared__ float sh[33];
    int lane = threadIdx.x & 31, w = threadIdx.x >> 5;
    #pragma unroll
    for (int o = 16; o; o >>= 1) v = fmaxf(v, __shfl_xor_sync(0xffffffffu, v, o));
    __syncthreads();
    if (lane == 0) sh[w] = v;
    __syncthreads();
    if (w == 0) {
        float x = (lane < 8) ? sh[lane] : __int_as_float(0xff800000);
        #pragma unroll
        for (int o = 4; o; o >>= 1) x = fmaxf(x, __shfl_xor_sync(0xffffffffu, x, o));
        if (lane == 0) sh[32] = x;
    }
    __syncthreads();
    return sh[32];
}

// ---------------- generic 8192x1024x1024 GEMM, 128x128 tiles, FFMA2 ----------------
// mode 0/1/2: write to g_Q/g_K/g_V in [B,H,S,64] layout;  mode 3: g_ctx @ W -> g_proj
__global__ void __launch_bounds__(256) gemm8192(const float* __restrict__ A,
                                                const float* __restrict__ W,
                                                int mode) {
    __shared__ float Ast[16][132];   // [k][m] transposed
    __shared__ float Ws[16][132];    // [k][n]
    const float* Ap = (mode == 3) ? g_ctx : A;
    int t = threadIdx.x, tx = t & 15, ty = t >> 4;
    int m0 = blockIdx.y * 128, n0 = blockIdx.x * 128;
    int arow = t >> 1, aq0 = (t & 1) * 2;   // A loader: row, k-quad pair
    int wr = t >> 5, wc = (t & 31) * 4;     // W loader

    u64t acc[8][4];
    #pragma unroll
    for (int i = 0; i < 8; i++)
        #pragma unroll
        for (int j = 0; j < 4; j++) acc[i][j] = 0ULL;

    for (int kt = 0; kt < 64; kt++) {
        float4 av0 = *(const float4*)&Ap[(size_t)(m0 + arow) * 1024 + kt * 16 + aq0 * 4];
        float4 av1 = *(const float4*)&Ap[(size_t)(m0 + arow) * 1024 + kt * 16 + aq0 * 4 + 4];
        float4 wv0 = *(const float4*)&W[(size_t)(kt * 16 + wr) * 1024 + n0 + wc];
        float4 wv1 = *(const float4*)&W[(size_t)(kt * 16 + wr + 8) * 1024 + n0 + wc];
        __syncthreads();
        Ast[aq0 * 4 + 0][arow] = av0.x; Ast[aq0 * 4 + 1][arow] = av0.y;
        Ast[aq0 * 4 + 2][arow] = av0.z; Ast[aq0 * 4 + 3][arow] = av0.w;
        Ast[aq0 * 4 + 4][arow] = av1.x; Ast[aq0 * 4 + 5][arow] = av1.y;
        Ast[aq0 * 4 + 6][arow] = av1.z; Ast[aq0 * 4 + 7][arow] = av1.w;
        *(float4*)&Ws[wr][wc] = wv0;
        *(float4*)&Ws[wr + 8][wc] = wv1;
        __syncthreads();
        #pragma unroll
        for (int kk = 0; kk < 16; kk++) {
            float4 af0 = *(const float4*)&Ast[kk][ty * 4];
            float4 af1 = *(const float4*)&Ast[kk][ty * 4 + 64];
            ulonglong2 b0 = *(const ulonglong2*)&Ws[kk][tx * 4];
            ulonglong2 b1 = *(const ulonglong2*)&Ws[kk][tx * 4 + 64];
            float ar[8] = {af0.x, af0.y, af0.z, af0.w, af1.x, af1.y, af1.z, af1.w};
            #pragma unroll
            for (int r = 0; r < 8; r++) {
                u64t ap = pk2(ar[r]);
                fma2(acc[r][0], ap, b0.x); fma2(acc[r][1], ap, b0.y);
                fma2(acc[r][2], ap, b1.x); fma2(acc[r][3], ap, b1.y);
            }
        }
    }

    if (mode <= 2) {
        float* O = (mode == 0) ? g_Q : (mode == 1) ? g_K : g_V;
        #pragma unroll
        for (int rg = 0; rg < 2; rg++)
            #pragma unroll
            for (int r = 0; r < 4; r++) {
                int m = m0 + ty * 4 + r + rg * 64;
                int b = m >> 11, s = m & 2047;
                #pragma unroll
                for (int cg = 0; cg < 2; cg++) {
                    int h = (n0 + cg * 64) >> 6;
                    float2 lo = upk2(acc[rg * 4 + r][cg * 2]);
                    float2 hi = upk2(acc[rg * 4 + r][cg * 2 + 1]);
                    float4 v = make_float4(lo.x, lo.y, hi.x, hi.y);
                    *(float4*)&O[((size_t)(b * Hq + h) * Sq + s) * 64 + tx * 4] = v;
                }
            }
    } else {
        #pragma unroll
        for (int rg = 0; rg < 2; rg++)
            #pragma unroll
            for (int r = 0; r < 4; r++) {
                int m = m0 + ty * 4 + r + rg * 64;
                #pragma unroll
                for (int cg = 0; cg < 2; cg++) {
                    float2 lo = upk2(acc[rg * 4 + r][cg * 2]);
                    float2 hi = upk2(acc[rg * 4 + r][cg * 2 + 1]);
                    float4 v = make_float4(lo.x, lo.y, hi.x, hi.y);
                    *(float4*)&g_proj[(size_t)m * 1024 + n0 + cg * 64 + tx * 4] = v;
                }
            }
    }
}

// ---------------- scores: raw (scaled+masked) Q K^T -> attn region, 128x128 tiles ----------------
__global__ void __launch_bounds__(256) scores_kernel(const unsigned char* __restrict__ mask,
                                                     float* __restrict__ attn) {
    float* Qs = smbuf;              // [64][132]  (Qs[d][q])
    float* Ks = smbuf + 64 * 132;   // [64][132]  (Ks[d][k])
    int t = threadIdx.x, tx = t & 15, ty = t >> 4;
    int bh = blockIdx.z, q0 = blockIdx.y * 128, k0 = blockIdx.x * 128;
    size_t base = (size_t)bh * Sq * 64;
    int lrow = t >> 1, lq0 = (t & 1) * 8;

    u64t acc[8][4];
    #pragma unroll
    for (int i = 0; i < 8; i++)
        #pragma unroll
        for (int j = 0; j < 4; j++) acc[i][j] = 0ULL;

    #pragma unroll
    for (int j = 0; j < 8; j++) {
        int dq = lq0 + j;
        float4 qv = *(const float4*)&g_Q[base + (size_t)(q0 + lrow) * 64 + dq * 4];
        Qs[(dq * 4 + 0) * 132 + lrow] = qv.x; Qs[(dq * 4 + 1) * 132 + lrow] = qv.y;
        Qs[(dq * 4 + 2) * 132 + lrow] = qv.z; Qs[(dq * 4 + 3) * 132 + lrow] = qv.w;
        float4 kv = *(const float4*)&g_K[base + (size_t)(k0 + lrow) * 64 + dq * 4];
        Ks[(dq * 4 + 0) * 132 + lrow] = kv.x; Ks[(dq * 4 + 1) * 132 + lrow] = kv.y;
        Ks[(dq * 4 + 2) * 132 + lrow] = kv.z; Ks[(dq * 4 + 3) * 132 + lrow] = kv.w;
    }
    __syncthreads();

    #pragma unroll 8
    for (int kk = 0; kk < 64; kk++) {
        float4 af0 = *(const float4*)&Qs[kk * 132 + ty * 4];
        float4 af1 = *(const float4*)&Qs[kk * 132 + ty * 4 + 64];
        ulonglong2 b0 = *(const ulonglong2*)&Ks[kk * 132 + tx * 4];
        ulonglong2 b1 = *(const ulonglong2*)&Ks[kk * 132 + tx * 4 + 64];
        float ar[8] = {af0.x, af0.y, af0.z, af0.w, af1.x, af1.y, af1.z, af1.w};
        #pragma unroll
        for (int r = 0; r < 8; r++) {
            u64t ap = pk2(ar[r]);
            fma2(acc[r][0], ap, b0.x); fma2(acc[r][1], ap, b0.y);
            fma2(acc[r][2], ap, b1.x); fma2(acc[r][3], ap, b1.y);
        }
    }

    int b = bh >> 4;
    #pragma unroll
    for (int rg = 0; rg < 2; rg++)
        #pragma unroll
        for (int r = 0; r < 4; r++) {
            int q = q0 + ty * 4 + r + rg * 64;
            #pragma unroll
            for (int cg = 0; cg < 2; cg++) {
                int kc = k0 + tx * 4 + cg * 64;
                unsigned int mk = *(const unsigned int*)&mask[(size_t)b * Sq * Sq + (size_t)q * Sq + kc];
                float2 lo = upk2(acc[rg * 4 + r][cg * 2]);
                float2 hi = upk2(acc[rg * 4 + r][cg * 2 + 1]);
                float4 v;
                v.x = (mk & 0xffu)         ? -1e9f : lo.x * 0.125f;
                v.y = ((mk >> 8) & 0xffu)  ? -1e9f : lo.y * 0.125f;
                v.z = ((mk >> 16) & 0xffu) ? -1e9f : hi.x * 0.125f;
                v.w = ((mk >> 24) & 0xffu) ? -1e9f : hi.y * 0.125f;
                *(float4*)&attn[(size_t)bh * Sq * Sq + (size_t)q * Sq + kc] = v;
            }
        }
}

// ---------------- per-row max / 1/sum(exp) ----------------
__global__ void __launch_bounds__(256) rowstats_kernel(const float* __restrict__ attn) {
    int r = blockIdx.x;
    int t = threadIdx.x;
    const float* row = attn + (size_t)r * Sq;
    float v[8];
    float mx = __int_as_float(0xff800000);
    #pragma unroll
    for (int i = 0; i < 8; i++) { v[i] = row[i * 256 + t]; mx = fmaxf(mx, v[i]); }
    mx = block_max(mx);
    float s = 0.0f;
    #pragma unroll
    for (int i = 0; i < 8; i++) s += __expf(v[i] - mx);
    s = block_sum(s);
    if (t == 0) { g_rowmax[r] = mx; g_rinv[r] = 1.0f / s; }
}

// ---------------- normalize attn in-place + context = P @ V, 256x64 tiles ----------------
__global__ void __launch_bounds__(256) av_kernel(float* __restrict__ attn) {
    float* Ps = smbuf;              // [64][256] swizzled  (Ps[k][q])
    float* Vs = smbuf + 64 * 256;   // [64][68]            (Vs[k][n])
    int t = threadIdx.x, tx = t & 7, ty = t >> 3;
    int bh = blockIdx.y, q0 = blockIdx.x * 256;
    size_t abase = (size_t)bh * Sq * Sq;
    size_t vbase = (size_t)bh * Sq * 64;
    int r0 = bh * Sq + q0;
    int tj = t & 15, pr0 = t >> 4;

    u64t acc[8][4];
    #pragma unroll
    for (int i = 0; i < 8; i++)
        #pragma unroll
        for (int j = 0; j < 4; j++) acc[i][j] = 0ULL;

    for (int kt = 0; kt < 32; kt++) {
        __syncthreads();
        // P tile: 256 q-rows x 64 k; exp-normalize, write probs back, store transposed+swizzled
        #pragma unroll
        for (int i = 0; i < 16; i++) {
            int pr = pr0 + i * 16;
            float mx = g_rowmax[r0 + pr];
            float ri = g_rinv[r0 + pr];
            size_t sidx = abase + (size_t)(q0 + pr) * Sq + kt * 64 + tj * 4;
            float4 sv = *(const float4*)&attn[sidx];
            float4 pv;
            pv.x = __expf(sv.x - mx) * ri;
            pv.y = __expf(sv.y - mx) * ri;
            pv.z = __expf(sv.z - mx) * ri;
            pv.w = __expf(sv.w - mx) * ri;
            *(float4*)&attn[sidx] = pv;  // final probabilities
            int swz = pr ^ ((tj & 7) << 2);
            Ps[(tj * 4 + 0) * 256 + swz] = pv.x;
            Ps[(tj * 4 + 1) * 256 + swz] = pv.y;
            Ps[(tj * 4 + 2) * 256 + swz] = pv.z;
            Ps[(tj * 4 + 3) * 256 + swz] = pv.w;
        }
        // V tile: 64 k x 64 n
        #pragma unroll
        for (int j = 0; j < 4; j++) {
            int fidx = t + 256 * j;
            int vr = fidx >> 4, vc = (fidx & 15) * 4;
            float4 vv = *(const float4*)&g_V[vbase + (size_t)(kt * 64 + vr) * 64 + vc];
            *(float4*)&Vs[vr * 68 + vc] = vv;
        }
        __syncthreads();
        #pragma unroll 8
        for (int kk = 0; kk < 64; kk++) {
            int sw = ((kk >> 2) & 7) << 2;
            int ao = kk * 256 + ((ty * 4) ^ sw);
            float4 af0 = *(const float4*)&Ps[ao];
            float4 af1 = *(const float4*)&Ps[ao + 128];
            ulonglong2 b0 = *(const ulonglong2*)&Vs[kk * 68 + tx * 4];
            ulonglong2 b1 = *(const ulonglong2*)&Vs[kk * 68 + tx * 4 + 32];
            float ar[8] = {af0.x, af0.y, af0.z, af0.w, af1.x, af1.y, af1.z, af1.w};
            #pragma unroll
            for (int r = 0; r < 8; r++) {
                u64t ap = pk2(ar[r]);
                fma2(acc[r][0], ap, b0.x); fma2(acc[r][1], ap, b0.y);
                fma2(acc[r][2], ap, b1.x); fma2(acc[r][3], ap, b1.y);
            }
        }
    }

    int b = bh >> 4, h = bh & 15;
    #pragma unroll
    for (int rg = 0; rg < 2; rg++)
        #pragma unroll
        for (int r = 0; r < 4; r++) {
            int q = q0 + ty * 4 + r + rg * 128;
            #pragma unroll
            for (int cg = 0; cg < 2; cg++) {
                float2 lo = upk2(acc[rg * 4 + r][cg * 2]);
                float2 hi = upk2(acc[rg * 4 + r][cg * 2 + 1]);
                float4 v = make_float4(lo.x, lo.y, hi.x, hi.y);
                *(float4*)&g_ctx[(size_t)(b * Sq + q) * 1024 + h * 64 + tx * 4 + cg * 32] = v;
            }
        }
}

// ---------------- residual + LayerNorm ----------------
__global__ void __launch_bounds__(256) ln_kernel(const float* __restrict__ inQ,
                                                 const float* __restrict__ gamma,
                                                 const float* __restrict__ beta,
                                                 float* __restrict__ out) {
    int m = blockIdx.x;
    int t = threadIdx.x;
    size_t base = (size_t)m * 1024;
    float x[4];
    float s = 0.0f;
    #pragma unroll
    for (int i = 0; i < 4; i++) {
        int c = i * 256 + t;
        x[i] = g_proj[base + c] + inQ[base + c];
        s += x[i];
    }
    s = block_sum(s);
    float mu = s * (1.0f / 1024.0f);
    float s2 = 0.0f;
    #pragma unroll
    for (int i = 0; i < 4; i++) { float d = x[i] - mu; s2 += d * d; }
    s2 = block_sum(s2);
    float rstd = rsqrtf(s2 * (1.0f / 1024.0f) + 1e-5f);
    #pragma unroll
    for (int i = 0; i < 4; i++) {
        int c = i * 256 + t;
        out[base + c] = (x[i] - mu) * rstd * gamma[c] + beta[c];
    }
}

// ---------------- launch ----------------
extern "C" void kernel_launch(void* const* d_in, const int* in_sizes, int n_in,
                              void* d_out, int out_size) {
    const float* inQ = (const float*)d_in[0];
    const float* inK = (const float*)d_in[1];
    const float* inV = (const float*)d_in[2];
    const unsigned char* mask = (const unsigned char*)d_in[3];
    const float* wQ = (const float*)d_in[4];
    const float* wK = (const float*)d_in[5];
    const float* wV = (const float*)d_in[6];
    const float* wO = (const float*)d_in[7];
    const float* gamma = (const float*)d_in[8];
    const float* beta = (const float*)d_in[9];
    float* out = (float*)d_out;
    float* attn = out + (size_t)Bq * Sq * Eq;  // tuple order: (out, attn)

    const int SC_SMEM = 2 * 64 * 132 * 4;            // 67,584 B
    const int AV_SMEM = (64 * 256 + 64 * 68) * 4;    // 82,944 B
    cudaFuncSetAttribute(scores_kernel, cudaFuncAttributeMaxDynamicSharedMemorySize, SC_SMEM);
    cudaFuncSetAttribute(av_kernel, cudaFuncAttributeMaxDynamicSharedMemorySize, AV_SMEM);

    dim3 blk(256);
    gemm8192<<<dim3(8, 64), blk>>>(inQ, wQ, 0);
    gemm8192<<<dim3(8, 64), blk>>>(inK, wK, 1);
    gemm8192<<<dim3(8, 64), blk>>>(inV, wV, 2);
    scores_kernel<<<dim3(16, 16, 64), blk, SC_SMEM>>>(mask, attn);
    rowstats_kernel<<<Bq * Hq * Sq, blk>>>(attn);
    av_kernel<<<dim3(8, 64), blk, AV_SMEM>>>(attn);
    gemm8192<<<dim3(8, 64), blk>>>(nullptr, wO, 3);
    ln_kernel<<<Bq * Sq, blk>>>(inQ, gamma, beta, out);
}

// round 4
// speedup vs baseline: 1.7723x; 1.7723x over previous
#include <cuda_runtime.h>
#include <cuda_bf16.h>
#include <stdint.h>

#define Bq 4
#define Sq 2048
#define Eq 1024
#define Hq 16

#define SW128(o) ((o) ^ (((o) >> 3) & 0x70))
#define SW256(o) ((o) ^ (((o) >> 4) & 0x70))

// ---------------- scratch ----------------
__device__ float g_Q[Bq*Hq*Sq*64];
__device__ float g_K[Bq*Hq*Sq*64];
__device__ float g_V[Bq*Hq*Sq*64];
__device__ float g_ctx[(size_t)Bq*Sq*Eq];
__device__ float g_proj[(size_t)Bq*Sq*Eq];
__device__ float g_rowmax[Bq*Hq*Sq];
__device__ float g_rinv[Bq*Hq*Sq];

// ---------------- mma / ldmatrix helpers ----------------
__device__ __forceinline__ void ldsm4(uint32_t& r0, uint32_t& r1, uint32_t& r2, uint32_t& r3, uint32_t a) {
    asm volatile("ldmatrix.sync.aligned.m8n8.x4.shared.b16 {%0,%1,%2,%3},[%4];"
                 : "=r"(r0), "=r"(r1), "=r"(r2), "=r"(r3) : "r"(a));
}
__device__ __forceinline__ void ldsm2(uint32_t& r0, uint32_t& r1, uint32_t a) {
    asm volatile("ldmatrix.sync.aligned.m8n8.x2.shared.b16 {%0,%1},[%2];"
                 : "=r"(r0), "=r"(r1) : "r"(a));
}
__device__ __forceinline__ void ldsm2t(uint32_t& r0, uint32_t& r1, uint32_t a) {
    asm volatile("ldmatrix.sync.aligned.m8n8.x2.trans.shared.b16 {%0,%1},[%2];"
                 : "=r"(r0), "=r"(r1) : "r"(a));
}
__device__ __forceinline__ void mmab(float* c, const uint32_t* a, const uint32_t* b) {
    asm volatile("mma.sync.aligned.m16n8k16.row.col.f32.bf16.bf16.f32 "
                 "{%0,%1,%2,%3},{%4,%5,%6,%7},{%8,%9},{%0,%1,%2,%3};"
                 : "+f"(c[0]), "+f"(c[1]), "+f"(c[2]), "+f"(c[3])
                 : "r"(a[0]), "r"(a[1]), "r"(a[2]), "r"(a[3]), "r"(b[0]), "r"(b[1]));
}
__device__ __forceinline__ uint32_t smaddr(const void* p) {
    return (uint32_t)__cvta_generic_to_shared(p);
}
// split fp32x4 -> bf16 hi quad + bf16 lo quad (packed 8B each)
__device__ __forceinline__ void split4(float4 v, uint2& h, uint2& l) {
    __nv_bfloat16 h0 = __float2bfloat16(v.x), h1 = __float2bfloat16(v.y);
    __nv_bfloat16 h2 = __float2bfloat16(v.z), h3 = __float2bfloat16(v.w);
    __nv_bfloat16 l0 = __float2bfloat16(v.x - __bfloat162float(h0));
    __nv_bfloat16 l1 = __float2bfloat16(v.y - __bfloat162float(h1));
    __nv_bfloat16 l2 = __float2bfloat16(v.z - __bfloat162float(h2));
    __nv_bfloat16 l3 = __float2bfloat16(v.w - __bfloat162float(h3));
    __nv_bfloat162 ph0(h0, h1), ph1(h2, h3), pl0(l0, l1), pl1(l2, l3);
    h.x = *(uint32_t*)&ph0; h.y = *(uint32_t*)&ph1;
    l.x = *(uint32_t*)&pl0; l.y = *(uint32_t*)&pl1;
}

// ---------------- block reductions ----------------
__device__ __forceinline__ float block_sum(float v) {
    __shared__ float sh[33];
    int lane = threadIdx.x & 31, w = threadIdx.x >> 5;
    #pragma unroll
    for (int o = 16; o; o >>= 1) v += __shfl_xor_sync(0xffffffffu, v, o);
    __syncthreads();
    if (lane == 0) sh[w] = v;
    __syncthreads();
    if (w == 0) {
        float x = (lane < 8) ? sh[lane] : 0.0f;
        #pragma unroll
        for (int o = 4; o; o >>= 1) x += __shfl_xor_sync(0xffffffffu, x, o);
        if (lane == 0) sh[32] = x;
    }
    __syncthreads();
    return sh[32];
}
__device__ __forceinline__ float block_max(float v) {
    __shared__ float sh[33];
    int lane = threadIdx.x & 31, w = threadIdx.x >> 5;
    #pragma unroll
    for (int o = 16; o; o >>= 1) v = fmaxf(v, __shfl_xor_sync(0xffffffffu, v, o));
    __syncthreads();
    if (lane == 0) sh[w] = v;
    __syncthreads();
    if (w == 0) {
        float x = (lane < 8) ? sh[lane] : __int_as_float(0xff800000);
        #pragma unroll
        for (int o = 4; o; o >>= 1) x = fmaxf(x, __shfl_xor_sync(0xffffffffu, x, o));
        if (lane == 0) sh[32] = x;
    }
    __syncthreads();
    return sh[32];
}

// ---------------- projections / output GEMM: [8192,1024]x[1024,1024] ----------------
// tile 128m x 128n, k-step 64.  mode 0/1/2 -> g_Q/g_K/g_V head layout, mode 3: g_ctx @ W -> g_proj
__global__ void __launch_bounds__(256) gemm8192(const float* __restrict__ A,
                                                const float* __restrict__ W,
                                                int mode) {
    extern __shared__ char smraw[];
    __nv_bfloat16* Ah = (__nv_bfloat16*)smraw;            // [128][64] SW128
    __nv_bfloat16* Al = Ah + 128 * 64;
    __nv_bfloat16* Bh = Al + 128 * 64;                    // [64][128] SW256
    __nv_bfloat16* Bl = Bh + 64 * 128;
    const float* Ap = (mode == 3) ? g_ctx : A;
    int t = threadIdx.x, lane = t & 31, wid = t >> 5;
    int wm = wid >> 2, wn = wid & 3;                      // 2 x 4 warps, warp tile 64m x 32n
    int m0 = blockIdx.y * 128, n0 = blockIdx.x * 128;
    uint32_t sAh = smaddr(Ah), sAl = smaddr(Al), sBh = smaddr(Bh), sBl = smaddr(Bl);

    float acc[4][4][4];
    #pragma unroll
    for (int i = 0; i < 4; i++)
        #pragma unroll
        for (int j = 0; j < 4; j++)
            #pragma unroll
            for (int e = 0; e < 4; e++) acc[i][j][e] = 0.0f;

    for (int kt = 0; kt < 16; kt++) {
        __syncthreads();
        // A tile: 128 rows x 64 k
        #pragma unroll
        for (int p = 0; p < 8; p++) {
            int idx = t + 256 * p;
            int r = idx >> 4, c4 = (idx & 15) * 4;
            float4 v = *(const float4*)&Ap[(size_t)(m0 + r) * 1024 + kt * 64 + c4];
            uint2 h, l; split4(v, h, l);
            uint32_t off = SW128(r * 128 + c4 * 2);
            *(uint2*)((char*)Ah + off) = h;
            *(uint2*)((char*)Al + off) = l;
        }
        // B tile: 64 k x 128 n  (natural [k][n], SW256 rows)
        #pragma unroll
        for (int p = 0; p < 8; p++) {
            int idx = t + 256 * p;
            int k = idx >> 5, c4 = (idx & 31) * 4;
            float4 v = *(const float4*)&W[(size_t)(kt * 64 + k) * 1024 + n0 + c4];
            uint2 h, l; split4(v, h, l);
            uint32_t off = SW256(k * 256 + c4 * 2);
            *(uint2*)((char*)Bh + off) = h;
            *(uint2*)((char*)Bl + off) = l;
        }
        __syncthreads();
        #pragma unroll
        for (int ks = 0; ks < 4; ks++) {
            uint32_t bhf[4][2], blf[4][2];
            #pragma unroll
            for (int in = 0; in < 4; in++) {
                int krow = ks * 16 + (lane & 15);
                int nb = (wn * 32 + in * 8) * 2;
                uint32_t off = SW256(krow * 256 + nb);
                ldsm2t(bhf[in][0], bhf[in][1], sBh + off);
                ldsm2t(blf[in][0], blf[in][1], sBl + off);
            }
            #pragma unroll
            for (int im = 0; im < 4; im++) {
                int arow = wm * 64 + im * 16 + (lane & 15);
                int acb = (ks * 16 + ((lane >> 4) << 3)) * 2;
                uint32_t off = SW128(arow * 128 + acb);
                uint32_t ah[4], al[4];
                ldsm4(ah[0], ah[1], ah[2], ah[3], sAh + off);
                ldsm4(al[0], al[1], al[2], al[3], sAl + off);
                #pragma unroll
                for (int in = 0; in < 4; in++) {
                    mmab(acc[im][in], ah, bhf[in]);
                    mmab(acc[im][in], al, bhf[in]);
                    mmab(acc[im][in], ah, blf[in]);
                }
            }
        }
    }

    int g = lane >> 2, c2 = (lane & 3) * 2;
    #pragma unroll
    for (int im = 0; im < 4; im++)
        #pragma unroll
        for (int in = 0; in < 4; in++)
            #pragma unroll
            for (int hh = 0; hh < 2; hh++) {
                int m = m0 + wm * 64 + im * 16 + g + hh * 8;
                int n = n0 + wn * 32 + in * 8 + c2;
                float2 v = make_float2(acc[im][in][hh * 2], acc[im][in][hh * 2 + 1]);
                if (mode <= 2) {
                    float* O = (mode == 0) ? g_Q : (mode == 1) ? g_K : g_V;
                    int b = m >> 11, s = m & 2047;
                    int h = n >> 6, d = n & 63;
                    *(float2*)&O[((size_t)(b * Hq + h) * Sq + s) * 64 + d] = v;
                } else {
                    *(float2*)&g_proj[(size_t)m * 1024 + n] = v;
                }
            }
}

// ---------------- scores: Q K^T (scaled+masked) -> attn ----------------
// tile 128q x 128k per block over (16,16,64)
__global__ void __launch_bounds__(256) scores_kernel(const unsigned char* __restrict__ mask,
                                                     float* __restrict__ attn) {
    extern __shared__ char smraw[];
    __nv_bfloat16* Qh = (__nv_bfloat16*)smraw;   // [128][64] SW128
    __nv_bfloat16* Ql = Qh + 128 * 64;
    __nv_bfloat16* Kh = Ql + 128 * 64;           // [128 kcol][64 d]  ([n][k] natural)
    __nv_bfloat16* Kl = Kh + 128 * 64;
    int t = threadIdx.x, lane = t & 31, wid = t >> 5;
    int wm = wid >> 2, wn = wid & 3;             // warp tile 64q x 32k
    int bh = blockIdx.z, q0 = blockIdx.y * 128, k0 = blockIdx.x * 128;
    size_t base = (size_t)bh * Sq * 64;
    uint32_t sQh = smaddr(Qh), sQl = smaddr(Ql), sKh = smaddr(Kh), sKl = smaddr(Kl);

    #pragma unroll
    for (int p = 0; p < 8; p++) {
        int idx = t + 256 * p;
        int r = idx >> 4, c4 = (idx & 15) * 4;
        uint32_t off = SW128(r * 128 + c4 * 2);
        float4 qv = *(const float4*)&g_Q[base + (size_t)(q0 + r) * 64 + c4];
        uint2 h, l; split4(qv, h, l);
        *(uint2*)((char*)Qh + off) = h; *(uint2*)((char*)Ql + off) = l;
        float4 kv = *(const float4*)&g_K[base + (size_t)(k0 + r) * 64 + c4];
        split4(kv, h, l);
        *(uint2*)((char*)Kh + off) = h; *(uint2*)((char*)Kl + off) = l;
    }
    __syncthreads();

    float acc[4][4][4];
    #pragma unroll
    for (int i = 0; i < 4; i++)
        #pragma unroll
        for (int j = 0; j < 4; j++)
            #pragma unroll
            for (int e = 0; e < 4; e++) acc[i][j][e] = 0.0f;

    #pragma unroll
    for (int ks = 0; ks < 4; ks++) {
        uint32_t bhf[4][2], blf[4][2];
        #pragma unroll
        for (int in = 0; in < 4; in++) {
            int nrow = wn * 32 + in * 8 + (lane & 7);
            int cb = (ks * 16 + (lane & 8)) * 2;
            uint32_t off = SW128(nrow * 128 + cb);
            ldsm2(bhf[in][0], bhf[in][1], sKh + off);
            ldsm2(blf[in][0], blf[in][1], sKl + off);
        }
        #pragma unroll
        for (int im = 0; im < 4; im++) {
            int arow = wm * 64 + im * 16 + (lane & 15);
            int acb = (ks * 16 + ((lane >> 4) << 3)) * 2;
            uint32_t off = SW128(arow * 128 + acb);
            uint32_t ah[4], al[4];
            ldsm4(ah[0], ah[1], ah[2], ah[3], sQh + off);
            ldsm4(al[0], al[1], al[2], al[3], sQl + off);
            #pragma unroll
            for (int in = 0; in < 4; in++) {
                mmab(acc[im][in], ah, bhf[in]);
                mmab(acc[im][in], al, bhf[in]);
                mmab(acc[im][in], ah, blf[in]);
            }
        }
    }

    int b = bh >> 4;
    int g = lane >> 2, c2 = (lane & 3) * 2;
    #pragma unroll
    for (int im = 0; im < 4; im++)
        #pragma unroll
        for (int in = 0; in < 4; in++)
            #pragma unroll
            for (int hh = 0; hh < 2; hh++) {
                int q = q0 + wm * 64 + im * 16 + g + hh * 8;
                int kc = k0 + wn * 32 + in * 8 + c2;
                unsigned short mk = *(const unsigned short*)&mask[(size_t)b * Sq * Sq + (size_t)q * Sq + kc];
                float2 v;
                v.x = (mk & 0xffu) ? -1e9f : acc[im][in][hh * 2] * 0.125f;
                v.y = ((mk >> 8) & 0xffu) ? -1e9f : acc[im][in][hh * 2 + 1] * 0.125f;
                *(float2*)&attn[(size_t)bh * Sq * Sq + (size_t)q * Sq + kc] = v;
            }
}

// ---------------- per-row max / 1/sum(exp) ----------------
__global__ void __launch_bounds__(256) rowstats_kernel(const float* __restrict__ attn) {
    int r = blockIdx.x, t = threadIdx.x;
    const float* row = attn + (size_t)r * Sq;
    float v[8];
    float mx = __int_as_float(0xff800000);
    #pragma unroll
    for (int i = 0; i < 8; i++) { v[i] = row[i * 256 + t]; mx = fmaxf(mx, v[i]); }
    mx = block_max(mx);
    float s = 0.0f;
    #pragma unroll
    for (int i = 0; i < 8; i++) s += __expf(v[i] - mx);
    s = block_sum(s);
    if (t == 0) { g_rowmax[r] = mx; g_rinv[r] = 1.0f / s; }
}

// ---------------- normalize attn in-place + context = P @ V ----------------
// tile 128q x 64n, k loop 2048 step 64
__global__ void __launch_bounds__(256) av_kernel(float* __restrict__ attn) {
    extern __shared__ char smraw[];
    __nv_bfloat16* Ph = (__nv_bfloat16*)smraw;   // [128][64] SW128
    __nv_bfloat16* Pl = Ph + 128 * 64;
    __nv_bfloat16* Vh = Pl + 128 * 64;           // [64 k][64 n] natural SW128
    __nv_bfloat16* Vl = Vh + 64 * 64;
    int t = threadIdx.x, lane = t & 31, wid = t >> 5;
    int wm = wid >> 1, wn = wid & 1;             // 4 x 2 warps, warp tile 32q x 32n
    int bh = blockIdx.y, q0 = blockIdx.x * 128;
    size_t abase = (size_t)bh * Sq * Sq;
    size_t vbase = (size_t)bh * Sq * 64;
    int r0 = bh * Sq + q0;
    uint32_t sPh = smaddr(Ph), sPl = smaddr(Pl), sVh = smaddr(Vh), sVl = smaddr(Vl);

    float acc[2][4][4];
    #pragma unroll
    for (int i = 0; i < 2; i++)
        #pragma unroll
        for (int j = 0; j < 4; j++)
            #pragma unroll
            for (int e = 0; e < 4; e++) acc[i][j][e] = 0.0f;

    for (int kt = 0; kt < 32; kt++) {
        __syncthreads();
        // P tile: exp-normalize 128x64, write probs back, split into smem
        #pragma unroll
        for (int p = 0; p < 8; p++) {
            int idx = t + 256 * p;
            int r = idx >> 4, c4 = (idx & 15) * 4;
            float mx = g_rowmax[r0 + r], ri = g_rinv[r0 + r];
            size_t sidx = abase + (size_t)(q0 + r) * Sq + kt * 64 + c4;
            float4 sv = *(const float4*)&attn[sidx];
            float4 pv;
            pv.x = __expf(sv.x - mx) * ri;
            pv.y = __expf(sv.y - mx) * ri;
            pv.z = __expf(sv.z - mx) * ri;
            pv.w = __expf(sv.w - mx) * ri;
            *(float4*)&attn[sidx] = pv;
            uint2 h, l; split4(pv, h, l);
            uint32_t off = SW128(r * 128 + c4 * 2);
            *(uint2*)((char*)Ph + off) = h;
            *(uint2*)((char*)Pl + off) = l;
        }
        // V tile 64x64
        #pragma unroll
        for (int p = 0; p < 4; p++) {
            int idx = t + 256 * p;
            int r = idx >> 4, c4 = (idx & 15) * 4;
            float4 vv = *(const float4*)&g_V[vbase + (size_t)(kt * 64 + r) * 64 + c4];
            uint2 h, l; split4(vv, h, l);
            uint32_t off = SW128(r * 128 + c4 * 2);
            *(uint2*)((char*)Vh + off) = h;
            *(uint2*)((char*)Vl + off) = l;
        }
        __syncthreads();
        #pragma unroll
        for (int ks = 0; ks < 4; ks++) {
            uint32_t bhf[4][2], blf[4][2];
            #pragma unroll
            for (int in = 0; in < 4; in++) {
                int krow = ks * 16 + (lane & 15);
                int nb = (wn * 32 + in * 8) * 2;
                uint32_t off = SW128(krow * 128 + nb);
                ldsm2t(bhf[in][0], bhf[in][1], sVh + off);
                ldsm2t(blf[in][0], blf[in][1], sVl + off);
            }
            #pragma unroll
            for (int im = 0; im < 2; im++) {
                int arow = wm * 32 + im * 16 + (lane & 15);
                int acb = (ks * 16 + ((lane >> 4) << 3)) * 2;
                uint32_t off = SW128(arow * 128 + acb);
                uint32_t ah[4], al[4];
                ldsm4(ah[0], ah[1], ah[2], ah[3], sPh + off);
                ldsm4(al[0], al[1], al[2], al[3], sPl + off);
                #pragma unroll
                for (int in = 0; in < 4; in++) {
                    mmab(acc[im][in], ah, bhf[in]);
                    mmab(acc[im][in], al, bhf[in]);
                    mmab(acc[im][in], ah, blf[in]);
                }
            }
        }
    }

    int b = bh >> 4, h = bh & 15;
    int g = lane >> 2, c2 = (lane & 3) * 2;
    #pragma unroll
    for (int im = 0; im < 2; im++)
        #pragma unroll
        for (int in = 0; in < 4; in++)
            #pragma unroll
            for (int hh = 0; hh < 2; hh++) {
                int q = q0 + wm * 32 + im * 16 + g + hh * 8;
                int n = wn * 32 + in * 8 + c2;
                float2 v = make_float2(acc[im][in][hh * 2], acc[im][in][hh * 2 + 1]);
                *(float2*)&g_ctx[(size_t)(b * Sq + q) * 1024 + h * 64 + n] = v;
            }
}

// ---------------- residual + LayerNorm ----------------
__global__ void __launch_bounds__(256) ln_kernel(const float* __restrict__ inQ,
                                                 const float* __restrict__ gamma,
                                                 const float* __restrict__ beta,
                                                 float* __restrict__ out) {
    int m = blockIdx.x, t = threadIdx.x;
    size_t base = (size_t)m * 1024;
    float x[4];
    float s = 0.0f;
    #pragma unroll
    for (int i = 0; i < 4; i++) {
        int c = i * 256 + t;
        x[i] = g_proj[base + c] + inQ[base + c];
        s += x[i];
    }
    s = block_sum(s);
    float mu = s * (1.0f / 1024.0f);
    float s2 = 0.0f;
    #pragma unroll
    for (int i = 0; i < 4; i++) { float d = x[i] - mu; s2 += d * d; }
    s2 = block_sum(s2);
    float rstd = rsqrtf(s2 * (1.0f / 1024.0f) + 1e-5f);
    #pragma unroll
    for (int i = 0; i < 4; i++) {
        int c = i * 256 + t;
        out[base + c] = (x[i] - mu) * rstd * gamma[c] + beta[c];
    }
}

// ---------------- launch ----------------
extern "C" void kernel_launch(void* const* d_in, const int* in_sizes, int n_in,
                              void* d_out, int out_size) {
    const float* inQ = (const float*)d_in[0];
    const float* inK = (const float*)d_in[1];
    const float* inV = (const float*)d_in[2];
    const unsigned char* mask = (const unsigned char*)d_in[3];
    const float* wQ = (const float*)d_in[4];
    const float* wK = (const float*)d_in[5];
    const float* wV = (const float*)d_in[6];
    const float* wO = (const float*)d_in[7];
    const float* gamma = (const float*)d_in[8];
    const float* beta = (const float*)d_in[9];
    float* out = (float*)d_out;
    float* attn = out + (size_t)Bq * Sq * Eq;

    const int GEMM_SMEM = (128 * 64 * 2 + 64 * 128 * 2) * 2;  // 65536
    const int SC_SMEM   = 4 * 128 * 64 * 2;                   // 65536
    const int AV_SMEM   = (2 * 128 * 64 + 2 * 64 * 64) * 2;   // 49152
    static int configured = 0;
    cudaFuncSetAttribute(gemm8192, cudaFuncAttributeMaxDynamicSharedMemorySize, GEMM_SMEM);
    cudaFuncSetAttribute(scores_kernel, cudaFuncAttributeMaxDynamicSharedMemorySize, SC_SMEM);
    cudaFuncSetAttribute(av_kernel, cudaFuncAttributeMaxDynamicSharedMemorySize, AV_SMEM);
    (void)configured;

    dim3 blk(256);
    gemm8192<<<dim3(8, 64), blk, GEMM_SMEM>>>(inQ, wQ, 0);
    gemm8192<<<dim3(8, 64), blk, GEMM_SMEM>>>(inK, wK, 1);
    gemm8192<<<dim3(8, 64), blk, GEMM_SMEM>>>(inV, wV, 2);
    scores_kernel<<<dim3(16, 16, 64), blk, SC_SMEM>>>(mask, attn);
    rowstats_kernel<<<Bq * Hq * Sq, blk>>>(attn);
    av_kernel<<<dim3(16, 64), blk, AV_SMEM>>>(attn);
    gemm8192<<<dim3(8, 64), blk, GEMM_SMEM>>>(nullptr, wO, 3);
    ln_kernel<<<Bq * Sq, blk>>>(inQ, gamma, beta, out);
}

// round 5
// speedup vs baseline: 2.3876x; 1.3472x over previous
#include <cuda_runtime.h>
#include <cuda_bf16.h>
#include <stdint.h>

#define Bq 4
#define Sq 2048
#define Eq 1024
#define Hq 16

#define SW128(o) ((o) ^ (((o) >> 3) & 0x70))
#define SW256(o) ((o) ^ (((o) >> 4) & 0x70))

// ---------------- scratch ----------------
__device__ float g_Q[Bq*Hq*Sq*64];
__device__ float g_K[Bq*Hq*Sq*64];
__device__ float g_V[Bq*Hq*Sq*64];
__device__ float g_ctx[(size_t)Bq*Sq*Eq];
__device__ float g_proj[(size_t)Bq*Sq*Eq];
__device__ float g_rowmax[Bq*Hq*Sq];
__device__ float g_rinv[Bq*Hq*Sq];
__device__ float2 g_pstat[(size_t)Bq*Hq*Sq*64];   // 64 partial (max,sumexp) per row

// ---------------- mma / ldmatrix helpers ----------------
__device__ __forceinline__ void ldsm4(uint32_t& r0, uint32_t& r1, uint32_t& r2, uint32_t& r3, uint32_t a) {
    asm volatile("ldmatrix.sync.aligned.m8n8.x4.shared.b16 {%0,%1,%2,%3},[%4];"
                 : "=r"(r0), "=r"(r1), "=r"(r2), "=r"(r3) : "r"(a));
}
__device__ __forceinline__ void ldsm2(uint32_t& r0, uint32_t& r1, uint32_t a) {
    asm volatile("ldmatrix.sync.aligned.m8n8.x2.shared.b16 {%0,%1},[%2];"
                 : "=r"(r0), "=r"(r1) : "r"(a));
}
__device__ __forceinline__ void ldsm2t(uint32_t& r0, uint32_t& r1, uint32_t a) {
    asm volatile("ldmatrix.sync.aligned.m8n8.x2.trans.shared.b16 {%0,%1},[%2];"
                 : "=r"(r0), "=r"(r1) : "r"(a));
}
__device__ __forceinline__ void mmab(float* c, const uint32_t* a, const uint32_t* b) {
    asm volatile("mma.sync.aligned.m16n8k16.row.col.f32.bf16.bf16.f32 "
                 "{%0,%1,%2,%3},{%4,%5,%6,%7},{%8,%9},{%0,%1,%2,%3};"
                 : "+f"(c[0]), "+f"(c[1]), "+f"(c[2]), "+f"(c[3])
                 : "r"(a[0]), "r"(a[1]), "r"(a[2]), "r"(a[3]), "r"(b[0]), "r"(b[1]));
}
__device__ __forceinline__ uint32_t smaddr(const void* p) {
    return (uint32_t)__cvta_generic_to_shared(p);
}
__device__ __forceinline__ void split4(float4 v, uint2& h, uint2& l) {
    __nv_bfloat16 h0 = __float2bfloat16(v.x), h1 = __float2bfloat16(v.y);
    __nv_bfloat16 h2 = __float2bfloat16(v.z), h3 = __float2bfloat16(v.w);
    __nv_bfloat16 l0 = __float2bfloat16(v.x - __bfloat162float(h0));
    __nv_bfloat16 l1 = __float2bfloat16(v.y - __bfloat162float(h1));
    __nv_bfloat16 l2 = __float2bfloat16(v.z - __bfloat162float(h2));
    __nv_bfloat16 l3 = __float2bfloat16(v.w - __bfloat162float(h3));
    __nv_bfloat162 ph0(h0, h1), ph1(h2, h3), pl0(l0, l1), pl1(l2, l3);
    h.x = *(uint32_t*)&ph0; h.y = *(uint32_t*)&ph1;
    l.x = *(uint32_t*)&pl0; l.y = *(uint32_t*)&pl1;
}

// ---------------- block reductions (ln kernel) ----------------
__device__ __forceinline__ float block_sum(float v) {
    __shared__ float sh[33];
    int lane = threadIdx.x & 31, w = threadIdx.x >> 5;
    #pragma unroll
    for (int o = 16; o; o >>= 1) v += __shfl_xor_sync(0xffffffffu, v, o);
    __syncthreads();
    if (lane == 0) sh[w] = v;
    __syncthreads();
    if (w == 0) {
        float x = (lane < 8) ? sh[lane] : 0.0f;
        #pragma unroll
        for (int o = 4; o; o >>= 1) x += __shfl_xor_sync(0xffffffffu, x, o);
        if (lane == 0) sh[32] = x;
    }
    __syncthreads();
    return sh[32];
}

// ---------------- projections / output GEMM, double-buffered ----------------
__global__ void __launch_bounds__(256) gemm8192(const float* __restrict__ A,
                                                const float* __restrict__ W,
                                                int mode) {
    extern __shared__ char smraw[];
    const float* Ap = (mode == 3) ? g_ctx : A;
    int t = threadIdx.x, lane = t & 31, wid = t >> 5;
    int wm = wid >> 2, wn = wid & 3;                 // 2x4 warps, 64m x 32n each
    int m0 = blockIdx.y * 128, n0 = blockIdx.x * 128;
    int ar = t >> 4, ac4 = (t & 15) * 4;
    int bk = t >> 5, bc4 = (t & 31) * 4;
    uint32_t sBase = smaddr(smraw);

    float4 pa[8], pb[8];
    float acc[4][4][4];
    #pragma unroll
    for (int i = 0; i < 4; i++)
        #pragma unroll
        for (int j = 0; j < 4; j++)
            #pragma unroll
            for (int e = 0; e < 4; e++) acc[i][j][e] = 0.0f;

    // prologue LDG kt=0
    #pragma unroll
    for (int p = 0; p < 8; p++) {
        pa[p] = *(const float4*)&Ap[(size_t)(m0 + ar + 16 * p) * 1024 + ac4];
        pb[p] = *(const float4*)&W[(size_t)(bk + 8 * p) * 1024 + n0 + bc4];
    }

    for (int kt = 0; kt < 16; kt++) {
        int buf = kt & 1;
        char* Ah = smraw + buf * 65536;
        char* Al = Ah + 16384;
        char* Bh = Al + 16384;
        char* Bl = Bh + 16384;
        // STS current tile
        #pragma unroll
        for (int p = 0; p < 8; p++) {
            uint2 h, l;
            split4(pa[p], h, l);
            uint32_t off = SW128((ar + 16 * p) * 128 + ac4 * 2);
            *(uint2*)(Ah + off) = h; *(uint2*)(Al + off) = l;
            split4(pb[p], h, l);
            uint32_t offb = SW256((bk + 8 * p) * 256 + bc4 * 2);
            *(uint2*)(Bh + offb) = h; *(uint2*)(Bl + offb) = l;
        }
        __syncthreads();
        // prefetch next tile
        if (kt < 15) {
            #pragma unroll
            for (int p = 0; p < 8; p++) {
                pa[p] = *(const float4*)&Ap[(size_t)(m0 + ar + 16 * p) * 1024 + (kt + 1) * 64 + ac4];
                pb[p] = *(const float4*)&W[(size_t)((kt + 1) * 64 + bk + 8 * p) * 1024 + n0 + bc4];
            }
        }
        // MMA on buf
        uint32_t sAh = sBase + buf * 65536, sAl = sAh + 16384;
        uint32_t sBh = sAl + 16384, sBl = sBh + 16384;
        #pragma unroll
        for (int ks = 0; ks < 4; ks++) {
            uint32_t bhf[4][2], blf[4][2];
            #pragma unroll
            for (int in = 0; in < 4; in++) {
                int krow = ks * 16 + (lane & 15);
                int nb = (wn * 32 + in * 8) * 2;
                uint32_t off = SW256(krow * 256 + nb);
                ldsm2t(bhf[in][0], bhf[in][1], sBh + off);
                ldsm2t(blf[in][0], blf[in][1], sBl + off);
            }
            #pragma unroll
            for (int im = 0; im < 4; im++) {
                int arow = wm * 64 + im * 16 + (lane & 15);
                int acb = (ks * 16 + ((lane >> 4) << 3)) * 2;
                uint32_t off = SW128(arow * 128 + acb);
                uint32_t ah[4], al[4];
                ldsm4(ah[0], ah[1], ah[2], ah[3], sAh + off);
                ldsm4(al[0], al[1], al[2], al[3], sAl + off);
                #pragma unroll
                for (int in = 0; in < 4; in++) {
                    mmab(acc[im][in], ah, bhf[in]);
                    mmab(acc[im][in], al, bhf[in]);
                    mmab(acc[im][in], ah, blf[in]);
                }
            }
        }
    }

    int g = lane >> 2, c2 = (lane & 3) * 2;
    #pragma unroll
    for (int im = 0; im < 4; im++)
        #pragma unroll
        for (int in = 0; in < 4; in++)
            #pragma unroll
            for (int hh = 0; hh < 2; hh++) {
                int m = m0 + wm * 64 + im * 16 + g + hh * 8;
                int n = n0 + wn * 32 + in * 8 + c2;
                float2 v = make_float2(acc[im][in][hh * 2], acc[im][in][hh * 2 + 1]);
                if (mode <= 2) {
                    float* O = (mode == 0) ? g_Q : (mode == 1) ? g_K : g_V;
                    int b = m >> 11, s = m & 2047;
                    int h = n >> 6, d = n & 63;
                    *(float2*)&O[((size_t)(b * Hq + h) * Sq + s) * 64 + d] = v;
                } else {
                    *(float2*)&g_proj[(size_t)m * 1024 + n] = v;
                }
            }
}

// ---------------- scores: Q K^T (scaled+masked) -> attn, with partial row stats ----------------
__global__ void __launch_bounds__(256) scores_kernel(const unsigned char* __restrict__ mask,
                                                     float* __restrict__ attn) {
    extern __shared__ char smraw[];
    char* Qh = smraw;                 // [128][64] SW128 bf16
    char* Ql = Qh + 16384;
    char* Kh = Ql + 16384;            // [128 kcol][64 d]
    char* Kl = Kh + 16384;
    int t = threadIdx.x, lane = t & 31, wid = t >> 5;
    int wm = wid >> 2, wn = wid & 3;
    int bh = blockIdx.z, q0 = blockIdx.y * 128, k0 = blockIdx.x * 128;
    size_t base = (size_t)bh * Sq * 64;
    uint32_t sQh = smaddr(Qh), sQl = smaddr(Ql), sKh = smaddr(Kh), sKl = smaddr(Kl);

    #pragma unroll
    for (int p = 0; p < 8; p++) {
        int r = (t >> 4) + 16 * p, c4 = (t & 15) * 4;
        uint32_t off = SW128(r * 128 + c4 * 2);
        float4 qv = *(const float4*)&g_Q[base + (size_t)(q0 + r) * 64 + c4];
        uint2 h, l; split4(qv, h, l);
        *(uint2*)(Qh + off) = h; *(uint2*)(Ql + off) = l;
        float4 kv = *(const float4*)&g_K[base + (size_t)(k0 + r) * 64 + c4];
        split4(kv, h, l);
        *(uint2*)(Kh + off) = h; *(uint2*)(Kl + off) = l;
    }
    __syncthreads();

    float acc[4][4][4];
    #pragma unroll
    for (int i = 0; i < 4; i++)
        #pragma unroll
        for (int j = 0; j < 4; j++)
            #pragma unroll
            for (int e = 0; e < 4; e++) acc[i][j][e] = 0.0f;

    #pragma unroll
    for (int ks = 0; ks < 4; ks++) {
        uint32_t bhf[4][2], blf[4][2];
        #pragma unroll
        for (int in = 0; in < 4; in++) {
            int nrow = wn * 32 + in * 8 + (lane & 7);
            int cb = (ks * 16 + (lane & 8)) * 2;
            uint32_t off = SW128(nrow * 128 + cb);
            ldsm2(bhf[in][0], bhf[in][1], sKh + off);
            ldsm2(blf[in][0], blf[in][1], sKl + off);
        }
        #pragma unroll
        for (int im = 0; im < 4; im++) {
            int arow = wm * 64 + im * 16 + (lane & 15);
            int acb = (ks * 16 + ((lane >> 4) << 3)) * 2;
            uint32_t off = SW128(arow * 128 + acb);
            uint32_t ah[4], al[4];
            ldsm4(ah[0], ah[1], ah[2], ah[3], sQh + off);
            ldsm4(al[0], al[1], al[2], al[3], sQl + off);
            #pragma unroll
            for (int in = 0; in < 4; in++) {
                mmab(acc[im][in], ah, bhf[in]);
                mmab(acc[im][in], al, bhf[in]);
                mmab(acc[im][in], ah, blf[in]);
            }
        }
    }

    int b = bh >> 4;
    int g = lane >> 2, c2 = (lane & 3) * 2;
    #pragma unroll
    for (int im = 0; im < 4; im++)
        #pragma unroll
        for (int hh = 0; hh < 2; hh++) {
            int q = q0 + wm * 64 + im * 16 + g + hh * 8;
            float vals[8];
            #pragma unroll
            for (int in = 0; in < 4; in++) {
                int kc = k0 + wn * 32 + in * 8 + c2;
                unsigned short mk = *(const unsigned short*)&mask[(size_t)b * Sq * Sq + (size_t)q * Sq + kc];
                float2 v;
                v.x = (mk & 0xffu) ? -1e9f : acc[im][in][hh * 2] * 0.125f;
                v.y = ((mk >> 8) & 0xffu) ? -1e9f : acc[im][in][hh * 2 + 1] * 0.125f;
                *(float2*)&attn[(size_t)bh * Sq * Sq + (size_t)q * Sq + kc] = v;
                vals[in * 2] = v.x; vals[in * 2 + 1] = v.y;
            }
            // partial (max, sumexp) over this warp's 32-k slice of row q
            float m = vals[0];
            #pragma unroll
            for (int i = 1; i < 8; i++) m = fmaxf(m, vals[i]);
            m = fmaxf(m, __shfl_xor_sync(0xffffffffu, m, 1));
            m = fmaxf(m, __shfl_xor_sync(0xffffffffu, m, 2));
            float s = 0.0f;
            #pragma unroll
            for (int i = 0; i < 8; i++) s += __expf(vals[i] - m);
            s += __shfl_xor_sync(0xffffffffu, s, 1);
            s += __shfl_xor_sync(0xffffffffu, s, 2);
            if ((lane & 3) == 0)
                g_pstat[((size_t)bh * Sq + q) * 64 + blockIdx.x * 4 + wn] = make_float2(m, s);
        }
}

// ---------------- fold 64 partials per row -> rowmax, rinv ----------------
__global__ void __launch_bounds__(256) reduce_stats() {
    int r = blockIdx.x * 8 + (threadIdx.x >> 5);
    int lane = threadIdx.x & 31;
    float2 a = g_pstat[(size_t)r * 64 + lane];
    float2 b = g_pstat[(size_t)r * 64 + 32 + lane];
    float m = fmaxf(a.x, b.x);
    #pragma unroll
    for (int o = 16; o; o >>= 1) m = fmaxf(m, __shfl_xor_sync(0xffffffffu, m, o));
    float s = a.y * __expf(a.x - m) + b.y * __expf(b.x - m);
    #pragma unroll
    for (int o = 16; o; o >>= 1) s += __shfl_xor_sync(0xffffffffu, s, o);
    if (lane == 0) { g_rowmax[r] = m; g_rinv[r] = 1.0f / s; }
}

// ---------------- normalize attn + context = P @ V, double-buffered ----------------
__global__ void __launch_bounds__(256) av_kernel(float* __restrict__ attn) {
    extern __shared__ char smraw[];
    int t = threadIdx.x, lane = t & 31, wid = t >> 5;
    int wm = wid >> 1, wn = wid & 1;            // 4x2 warps, 32q x 32n each
    int bh = blockIdx.y, q0 = blockIdx.x * 128;
    size_t abase = (size_t)bh * Sq * Sq;
    size_t vbase = (size_t)bh * Sq * 64;
    int r0 = bh * Sq + q0;
    uint32_t sBase = smaddr(smraw);
    int lr = t >> 4, c4 = (t & 15) * 4;

    float mxv[8], riv[8];
    #pragma unroll
    for (int p = 0; p < 8; p++) {
        mxv[p] = g_rowmax[r0 + lr + 16 * p];
        riv[p] = g_rinv[r0 + lr + 16 * p];
    }

    float acc[2][4][4];
    #pragma unroll
    for (int i = 0; i < 2; i++)
        #pragma unroll
        for (int j = 0; j < 4; j++)
            #pragma unroll
            for (int e = 0; e < 4; e++) acc[i][j][e] = 0.0f;

    float4 sv[8], vv[4];
    #pragma unroll
    for (int p = 0; p < 8; p++)
        sv[p] = *(const float4*)&attn[abase + (size_t)(q0 + lr + 16 * p) * Sq + c4];
    #pragma unroll
    for (int p = 0; p < 4; p++)
        vv[p] = *(const float4*)&g_V[vbase + (size_t)(lr + 16 * p) * 64 + c4];

    for (int kt = 0; kt < 32; kt++) {
        int buf = kt & 1;
        char* Ph = smraw + buf * 49152;
        char* Pl = Ph + 16384;
        char* Vh = Pl + 16384;
        char* Vl = Vh + 8192;
        // process current tile: exp-normalize, write probs, split to smem
        #pragma unroll
        for (int p = 0; p < 8; p++) {
            float4 pv;
            pv.x = __expf(sv[p].x - mxv[p]) * riv[p];
            pv.y = __expf(sv[p].y - mxv[p]) * riv[p];
            pv.z = __expf(sv[p].z - mxv[p]) * riv[p];
            pv.w = __expf(sv[p].w - mxv[p]) * riv[p];
            *(float4*)&attn[abase + (size_t)(q0 + lr + 16 * p) * Sq + kt * 64 + c4] = pv;
            uint2 h, l; split4(pv, h, l);
            uint32_t off = SW128((lr + 16 * p) * 128 + c4 * 2);
            *(uint2*)(Ph + off) = h; *(uint2*)(Pl + off) = l;
        }
        #pragma unroll
        for (int p = 0; p < 4; p++) {
            uint2 h, l; split4(vv[p], h, l);
            uint32_t off = SW128((lr + 16 * p) * 128 + c4 * 2);
            *(uint2*)(Vh + off) = h; *(uint2*)(Vl + off) = l;
        }
        __syncthreads();
        // prefetch next tile
        if (kt < 31) {
            #pragma unroll
            for (int p = 0; p < 8; p++)
                sv[p] = *(const float4*)&attn[abase + (size_t)(q0 + lr + 16 * p) * Sq + (kt + 1) * 64 + c4];
            #pragma unroll
            for (int p = 0; p < 4; p++)
                vv[p] = *(const float4*)&g_V[vbase + (size_t)((kt + 1) * 64 + lr + 16 * p) * 64 + c4];
        }
        // MMA on buf
        uint32_t sPh = sBase + buf * 49152, sPl = sPh + 16384;
        uint32_t sVh = sPl + 16384, sVl = sVh + 8192;
        #pragma unroll
        for (int ks = 0; ks < 4; ks++) {
            uint32_t bhf[4][2], blf[4][2];
            #pragma unroll
            for (int in = 0; in < 4; in++) {
                int krow = ks * 16 + (lane & 15);
                int nb = (wn * 32 + in * 8) * 2;
                uint32_t off = SW128(krow * 128 + nb);
                ldsm2t(bhf[in][0], bhf[in][1], sVh + off);
                ldsm2t(blf[in][0], blf[in][1], sVl + off);
            }
            #pragma unroll
            for (int im = 0; im < 2; im++) {
                int arow = wm * 32 + im * 16 + (lane & 15);
                int acb = (ks * 16 + ((lane >> 4) << 3)) * 2;
                uint32_t off = SW128(arow * 128 + acb);
                uint32_t ah[4], al[4];
                ldsm4(ah[0], ah[1], ah[2], ah[3], sPh + off);
                ldsm4(al[0], al[1], al[2], al[3], sPl + off);
                #pragma unroll
                for (int in = 0; in < 4; in++) {
                    mmab(acc[im][in], ah, bhf[in]);
                    mmab(acc[im][in], al, bhf[in]);
                    mmab(acc[im][in], ah, blf[in]);
                }
            }
        }
    }

    int b = bh >> 4, h = bh & 15;
    int g = lane >> 2, c2 = (lane & 3) * 2;
    #pragma unroll
    for (int im = 0; im < 2; im++)
        #pragma unroll
        for (int in = 0; in < 4; in++)
            #pragma unroll
            for (int hh = 0; hh < 2; hh++) {
                int q = q0 + wm * 32 + im * 16 + g + hh * 8;
                int n = wn * 32 + in * 8 + c2;
                float2 v = make_float2(acc[im][in][hh * 2], acc[im][in][hh * 2 + 1]);
                *(float2*)&g_ctx[(size_t)(b * Sq + q) * 1024 + h * 64 + n] = v;
            }
}

// ---------------- residual + LayerNorm ----------------
__global__ void __launch_bounds__(256) ln_kernel(const float* __restrict__ inQ,
                                                 const float* __restrict__ gamma,
                                                 const float* __restrict__ beta,
                                                 float* __restrict__ out) {
    int m = blockIdx.x, t = threadIdx.x;
    size_t base = (size_t)m * 1024;
    float x[4];
    float s = 0.0f;
    #pragma unroll
    for (int i = 0; i < 4; i++) {
        int c = i * 256 + t;
        x[i] = g_proj[base + c] + inQ[base + c];
        s += x[i];
    }
    s = block_sum(s);
    float mu = s * (1.0f / 1024.0f);
    float s2 = 0.0f;
    #pragma unroll
    for (int i = 0; i < 4; i++) { float d = x[i] - mu; s2 += d * d; }
    s2 = block_sum(s2);
    float rstd = rsqrtf(s2 * (1.0f / 1024.0f) + 1e-5f);
    #pragma unroll
    for (int i = 0; i < 4; i++) {
        int c = i * 256 + t;
        out[base + c] = (x[i] - mu) * rstd * gamma[c] + beta[c];
    }
}

// ---------------- launch ----------------
extern "C" void kernel_launch(void* const* d_in, const int* in_sizes, int n_in,
                              void* d_out, int out_size) {
    const float* inQ = (const float*)d_in[0];
    const float* inK = (const float*)d_in[1];
    const float* inV = (const float*)d_in[2];
    const unsigned char* mask = (const unsigned char*)d_in[3];
    const float* wQ = (const float*)d_in[4];
    const float* wK = (const float*)d_in[5];
    const float* wV = (const float*)d_in[6];
    const float* wO = (const float*)d_in[7];
    const float* gamma = (const float*)d_in[8];
    const float* beta = (const float*)d_in[9];
    float* out = (float*)d_out;
    float* attn = out + (size_t)Bq * Sq * Eq;

    const int GEMM_SMEM = 131072;  // 2 x (Ah+Al+Bh+Bl) 64KB
    const int SC_SMEM   = 65536;
    const int AV_SMEM   = 98304;   // 2 x 48KB
    cudaFuncSetAttribute(gemm8192, cudaFuncAttributeMaxDynamicSharedMemorySize, GEMM_SMEM);
    cudaFuncSetAttribute(scores_kernel, cudaFuncAttributeMaxDynamicSharedMemorySize, SC_SMEM);
    cudaFuncSetAttribute(av_kernel, cudaFuncAttributeMaxDynamicSharedMemorySize, AV_SMEM);

    dim3 blk(256);
    gemm8192<<<dim3(8, 64), blk, GEMM_SMEM>>>(inQ, wQ, 0);
    gemm8192<<<dim3(8, 64), blk, GEMM_SMEM>>>(inK, wK, 1);
    gemm8192<<<dim3(8, 64), blk, GEMM_SMEM>>>(inV, wV, 2);
    scores_kernel<<<dim3(16, 16, 64), blk, SC_SMEM>>>(mask, attn);
    reduce_stats<<<Bq * Hq * Sq / 8, blk>>>();
    av_kernel<<<dim3(16, 64), blk, AV_SMEM>>>(attn);
    gemm8192<<<dim3(8, 64), blk, GEMM_SMEM>>>(nullptr, wO, 3);
    ln_kernel<<<Bq * Sq, blk>>>(inQ, gamma, beta, out);
}

// round 7
// speedup vs baseline: 2.4115x; 1.0100x over previous
#include <cuda_runtime.h>
#include <cuda_bf16.h>
#include <stdint.h>

#define Bq 4
#define Sq 2048
#define Eq 1024
#define Hq 16

#define SW128(o) ((o) ^ (((o) >> 3) & 0x70))
#define SW256(o) ((o) ^ (((o) >> 4) & 0x70))

// ---------------- scratch ----------------
__device__ float g_Q[Bq*Hq*Sq*64];
__device__ float g_K[Bq*Hq*Sq*64];
__device__ float g_V[Bq*Hq*Sq*64];
__device__ float g_ctx[(size_t)Bq*Sq*Eq];
__device__ float g_proj[(size_t)Bq*Sq*Eq];
__device__ float g_rowmax[Bq*Hq*Sq];
__device__ float g_rinv[Bq*Hq*Sq];
__device__ float2 g_pstat[(size_t)Bq*Hq*Sq*64];   // 64 partial (max,sumexp) per row

// ---------------- mma / ldmatrix helpers ----------------
__device__ __forceinline__ void ldsm4(uint32_t& r0, uint32_t& r1, uint32_t& r2, uint32_t& r3, uint32_t a) {
    asm volatile("ldmatrix.sync.aligned.m8n8.x4.shared.b16 {%0,%1,%2,%3},[%4];"
                 : "=r"(r0), "=r"(r1), "=r"(r2), "=r"(r3) : "r"(a));
}
__device__ __forceinline__ void ldsm2(uint32_t& r0, uint32_t& r1, uint32_t a) {
    asm volatile("ldmatrix.sync.aligned.m8n8.x2.shared.b16 {%0,%1},[%2];"
                 : "=r"(r0), "=r"(r1) : "r"(a));
}
__device__ __forceinline__ void ldsm2t(uint32_t& r0, uint32_t& r1, uint32_t a) {
    asm volatile("ldmatrix.sync.aligned.m8n8.x2.trans.shared.b16 {%0,%1},[%2];"
                 : "=r"(r0), "=r"(r1) : "r"(a));
}
__device__ __forceinline__ void mmab(float* c, const uint32_t* a, const uint32_t* b) {
    asm volatile("mma.sync.aligned.m16n8k16.row.col.f32.bf16.bf16.f32 "
                 "{%0,%1,%2,%3},{%4,%5,%6,%7},{%8,%9},{%0,%1,%2,%3};"
                 : "+f"(c[0]), "+f"(c[1]), "+f"(c[2]), "+f"(c[3])
                 : "r"(a[0]), "r"(a[1]), "r"(a[2]), "r"(a[3]), "r"(b[0]), "r"(b[1]));
}
__device__ __forceinline__ uint32_t smaddr(const void* p) {
    return (uint32_t)__cvta_generic_to_shared(p);
}
__device__ __forceinline__ void split4(float4 v, uint2& h, uint2& l) {
    __nv_bfloat16 h0 = __float2bfloat16(v.x), h1 = __float2bfloat16(v.y);
    __nv_bfloat16 h2 = __float2bfloat16(v.z), h3 = __float2bfloat16(v.w);
    __nv_bfloat16 l0 = __float2bfloat16(v.x - __bfloat162float(h0));
    __nv_bfloat16 l1 = __float2bfloat16(v.y - __bfloat162float(h1));
    __nv_bfloat16 l2 = __float2bfloat16(v.z - __bfloat162float(h2));
    __nv_bfloat16 l3 = __float2bfloat16(v.w - __bfloat162float(h3));
    __nv_bfloat162 ph0(h0, h1), ph1(h2, h3), pl0(l0, l1), pl1(l2, l3);
    h.x = *(uint32_t*)&ph0; h.y = *(uint32_t*)&ph1;
    l.x = *(uint32_t*)&pl0; l.y = *(uint32_t*)&pl1;
}

// ---------------- block reductions (ln kernel) ----------------
__device__ __forceinline__ float block_sum(float v) {
    __shared__ float sh[33];
    int lane = threadIdx.x & 31, w = threadIdx.x >> 5;
    #pragma unroll
    for (int o = 16; o; o >>= 1) v += __shfl_xor_sync(0xffffffffu, v, o);
    __syncthreads();
    if (lane == 0) sh[w] = v;
    __syncthreads();
    if (w == 0) {
        float x = (lane < 8) ? sh[lane] : 0.0f;
        #pragma unroll
        for (int o = 4; o; o >>= 1) x += __shfl_xor_sync(0xffffffffu, x, o);
        if (lane == 0) sh[32] = x;
    }
    __syncthreads();
    return sh[32];
}

// ---------------- projections / output GEMM, double-buffered ----------------
__global__ void __launch_bounds__(256) gemm8192(const float* __restrict__ A,
                                                const float* __restrict__ W,
                                                int mode) {
    extern __shared__ char smraw[];
    const float* Ap = (mode == 3) ? g_ctx : A;
    int t = threadIdx.x, lane = t & 31, wid = t >> 5;
    int wm = wid >> 2, wn = wid & 3;                 // 2x4 warps, 64m x 32n each
    int m0 = blockIdx.y * 128, n0 = blockIdx.x * 128;
    int ar = t >> 4, ac4 = (t & 15) * 4;
    int bk = t >> 5, bc4 = (t & 31) * 4;
    uint32_t sBase = smaddr(smraw);

    float4 pa[8], pb[8];
    float acc[4][4][4];
    #pragma unroll
    for (int i = 0; i < 4; i++)
        #pragma unroll
        for (int j = 0; j < 4; j++)
            #pragma unroll
            for (int e = 0; e < 4; e++) acc[i][j][e] = 0.0f;

    #pragma unroll
    for (int p = 0; p < 8; p++) {
        pa[p] = *(const float4*)&Ap[(size_t)(m0 + ar + 16 * p) * 1024 + ac4];
        pb[p] = *(const float4*)&W[(size_t)(bk + 8 * p) * 1024 + n0 + bc4];
    }

    for (int kt = 0; kt < 16; kt++) {
        int buf = kt & 1;
        char* Ah = smraw + buf * 65536;
        char* Al = Ah + 16384;
        char* Bh = Al + 16384;
        char* Bl = Bh + 16384;
        #pragma unroll
        for (int p = 0; p < 8; p++) {
            uint2 h, l;
            split4(pa[p], h, l);
            uint32_t off = SW128((ar + 16 * p) * 128 + ac4 * 2);
            *(uint2*)(Ah + off) = h; *(uint2*)(Al + off) = l;
            split4(pb[p], h, l);
            uint32_t offb = SW256((bk + 8 * p) * 256 + bc4 * 2);
            *(uint2*)(Bh + offb) = h; *(uint2*)(Bl + offb) = l;
        }
        __syncthreads();
        if (kt < 15) {
            #pragma unroll
            for (int p = 0; p < 8; p++) {
                pa[p] = *(const float4*)&Ap[(size_t)(m0 + ar + 16 * p) * 1024 + (kt + 1) * 64 + ac4];
                pb[p] = *(const float4*)&W[(size_t)((kt + 1) * 64 + bk + 8 * p) * 1024 + n0 + bc4];
            }
        }
        uint32_t sAh = sBase + buf * 65536, sAl = sAh + 16384;
        uint32_t sBh = sAl + 16384, sBl = sBh + 16384;
        #pragma unroll
        for (int ks = 0; ks < 4; ks++) {
            uint32_t bhf[4][2], blf[4][2];
            #pragma unroll
            for (int in = 0; in < 4; in++) {
                int krow = ks * 16 + (lane & 15);
                int nb = (wn * 32 + in * 8) * 2;
                uint32_t off = SW256(krow * 256 + nb);
                ldsm2t(bhf[in][0], bhf[in][1], sBh + off);
                ldsm2t(blf[in][0], blf[in][1], sBl + off);
            }
            #pragma unroll
            for (int im = 0; im < 4; im++) {
                int arow = wm * 64 + im * 16 + (lane & 15);
                int acb = (ks * 16 + ((lane >> 4) << 3)) * 2;
                uint32_t off = SW128(arow * 128 + acb);
                uint32_t ah[4], al[4];
                ldsm4(ah[0], ah[1], ah[2], ah[3], sAh + off);
                ldsm4(al[0], al[1], al[2], al[3], sAl + off);
                #pragma unroll
                for (int in = 0; in < 4; in++) {
                    mmab(acc[im][in], ah, bhf[in]);
                    mmab(acc[im][in], al, bhf[in]);
                    mmab(acc[im][in], ah, blf[in]);
                }
            }
        }
    }

    int g = lane >> 2, c2 = (lane & 3) * 2;
    #pragma unroll
    for (int im = 0; im < 4; im++)
        #pragma unroll
        for (int in = 0; in < 4; in++)
            #pragma unroll
            for (int hh = 0; hh < 2; hh++) {
                int m = m0 + wm * 64 + im * 16 + g + hh * 8;
                int n = n0 + wn * 32 + in * 8 + c2;
                float2 v = make_float2(acc[im][in][hh * 2], acc[im][in][hh * 2 + 1]);
                if (mode <= 2) {
                    float* O = (mode == 0) ? g_Q : (mode == 1) ? g_K : g_V;
                    int b = m >> 11, s = m & 2047;
                    int h = n >> 6, d = n & 63;
                    *(float2*)&O[((size_t)(b * Hq + h) * Sq + s) * 64 + d] = v;
                } else {
                    *(float2*)&g_proj[(size_t)m * 1024 + n] = v;
                }
            }
}

// ---------------- scores: Q K^T (scaled+masked) -> attn, with partial row stats ----------------
__global__ void __launch_bounds__(256, 2) scores_kernel(const unsigned char* __restrict__ mask,
                                                        float* __restrict__ attn) {
    extern __shared__ char smraw[];
    char* Qh = smraw;                 // [128][64] SW128 bf16
    char* Ql = Qh + 16384;
    char* Kh = Ql + 16384;            // [128 kcol][64 d]
    char* Kl = Kh + 16384;
    int t = threadIdx.x, lane = t & 31, wid = t >> 5;
    int wm = wid >> 2, wn = wid & 3;
    int bh = blockIdx.z, q0 = blockIdx.y * 128, k0 = blockIdx.x * 128;
    size_t base = (size_t)bh * Sq * 64;
    uint32_t sQh = smaddr(Qh), sQl = smaddr(Ql), sKh = smaddr(Kh), sKl = smaddr(Kl);

    #pragma unroll
    for (int p = 0; p < 8; p++) {
        int r = (t >> 4) + 16 * p, c4 = (t & 15) * 4;
        uint32_t off = SW128(r * 128 + c4 * 2);
        float4 qv = *(const float4*)&g_Q[base + (size_t)(q0 + r) * 64 + c4];
        uint2 h, l; split4(qv, h, l);
        *(uint2*)(Qh + off) = h; *(uint2*)(Ql + off) = l;
        float4 kv = *(const float4*)&g_K[base + (size_t)(k0 + r) * 64 + c4];
        split4(kv, h, l);
        *(uint2*)(Kh + off) = h; *(uint2*)(Kl + off) = l;
    }
    __syncthreads();

    float acc[4][4][4];
    #pragma unroll
    for (int i = 0; i < 4; i++)
        #pragma unroll
        for (int j = 0; j < 4; j++)
            #pragma unroll
            for (int e = 0; e < 4; e++) acc[i][j][e] = 0.0f;

    #pragma unroll
    for (int ks = 0; ks < 4; ks++) {
        uint32_t bhf[4][2], blf[4][2];
        #pragma unroll
        for (int in = 0; in < 4; in++) {
            int nrow = wn * 32 + in * 8 + (lane & 7);
            int cb = (ks * 16 + (lane & 8)) * 2;
            uint32_t off = SW128(nrow * 128 + cb);
            ldsm2(bhf[in][0], bhf[in][1], sKh + off);
            ldsm2(blf[in][0], blf[in][1], sKl + off);
        }
        #pragma unroll
        for (int im = 0; im < 4; im++) {
            int arow = wm * 64 + im * 16 + (lane & 15);
            int acb = (ks * 16 + ((lane >> 4) << 3)) * 2;
            uint32_t off = SW128(arow * 128 + acb);
            uint32_t ah[4], al[4];
            ldsm4(ah[0], ah[1], ah[2], ah[3], sQh + off);
            ldsm4(al[0], al[1], al[2], al[3], sQl + off);
            #pragma unroll
            for (int in = 0; in < 4; in++) {
                mmab(acc[im][in], ah, bhf[in]);
                mmab(acc[im][in], al, bhf[in]);
                mmab(acc[im][in], ah, blf[in]);
            }
        }
    }

    int b = bh >> 4;
    int g = lane >> 2, c2 = (lane & 3) * 2;
    #pragma unroll
    for (int im = 0; im < 4; im++)
        #pragma unroll
        for (int hh = 0; hh < 2; hh++) {
            int q = q0 + wm * 64 + im * 16 + g + hh * 8;
            float vals[8];
            #pragma unroll
            for (int in = 0; in < 4; in++) {
                int kc = k0 + wn * 32 + in * 8 + c2;
                unsigned short mk = *(const unsigned short*)&mask[(size_t)b * Sq * Sq + (size_t)q * Sq + kc];
                float2 v;
                v.x = (mk & 0xffu) ? -1e9f : acc[im][in][hh * 2] * 0.125f;
                v.y = ((mk >> 8) & 0xffu) ? -1e9f : acc[im][in][hh * 2 + 1] * 0.125f;
                *(float2*)&attn[(size_t)bh * Sq * Sq + (size_t)q * Sq + kc] = v;
                vals[in * 2] = v.x; vals[in * 2 + 1] = v.y;
            }
            float m = vals[0];
            #pragma unroll
            for (int i = 1; i < 8; i++) m = fmaxf(m, vals[i]);
            m = fmaxf(m, __shfl_xor_sync(0xffffffffu, m, 1));
            m = fmaxf(m, __shfl_xor_sync(0xffffffffu, m, 2));
            float s = 0.0f;
            #pragma unroll
            for (int i = 0; i < 8; i++) s += __expf(vals[i] - m);
            s += __shfl_xor_sync(0xffffffffu, s, 1);
            s += __shfl_xor_sync(0xffffffffu, s, 2);
            if ((lane & 3) == 0)
                g_pstat[((size_t)bh * Sq + q) * 64 + blockIdx.x * 4 + wn] = make_float2(m, s);
        }
}

// ---------------- fold 64 partials per row -> rowmax, rinv ----------------
__global__ void __launch_bounds__(256) reduce_stats() {
    int r = blockIdx.x * 8 + (threadIdx.x >> 5);
    int lane = threadIdx.x & 31;
    float2 a = g_pstat[(size_t)r * 64 + lane];
    float2 b = g_pstat[(size_t)r * 64 + 32 + lane];
    float m = fmaxf(a.x, b.x);
    #pragma unroll
    for (int o = 16; o; o >>= 1) m = fmaxf(m, __shfl_xor_sync(0xffffffffu, m, o));
    float s = a.y * __expf(a.x - m) + b.y * __expf(b.x - m);
    #pragma unroll
    for (int o = 16; o; o >>= 1) s += __shfl_xor_sync(0xffffffffu, s, o);
    if (lane == 0) { g_rowmax[r] = m; g_rinv[r] = 1.0f / s; }
}

// ---------------- normalize attn + context = P @ V, double-buffered ----------------
__global__ void __launch_bounds__(256, 2) av_kernel(float* __restrict__ attn) {
    extern __shared__ char smraw[];
    int t = threadIdx.x, lane = t & 31, wid = t >> 5;
    int wm = wid >> 1, wn = wid & 1;            // 4x2 warps, 32q x 32n each
    int bh = blockIdx.y, q0 = blockIdx.x * 128;
    size_t abase = (size_t)bh * Sq * Sq;
    size_t vbase = (size_t)bh * Sq * 64;
    int r0 = bh * Sq + q0;
    uint32_t sBase = smaddr(smraw);
    int lr = t >> 4, c4 = (t & 15) * 4;

    float mxv[8], riv[8];
    #pragma unroll
    for (int p = 0; p < 8; p++) {
        mxv[p] = g_rowmax[r0 + lr + 16 * p];
        riv[p] = g_rinv[r0 + lr + 16 * p];
    }

    float acc[2][4][4];
    #pragma unroll
    for (int i = 0; i < 2; i++)
        #pragma unroll
        for (int j = 0; j < 4; j++)
            #pragma unroll
            for (int e = 0; e < 4; e++) acc[i][j][e] = 0.0f;

    float4 sv[8], vv[4];
    #pragma unroll
    for (int p = 0; p < 8; p++)
        sv[p] = *(const float4*)&attn[abase + (size_t)(q0 + lr + 16 * p) * Sq + c4];
    #pragma unroll
    for (int p = 0; p < 4; p++)
        vv[p] = *(const float4*)&g_V[vbase + (size_t)(lr + 16 * p) * 64 + c4];

    for (int kt = 0; kt < 32; kt++) {
        int buf = kt & 1;
        char* Ph = smraw + buf * 49152;
        char* Pl = Ph + 16384;
        char* Vh = Pl + 16384;
        char* Vl = Vh + 8192;
        #pragma unroll
        for (int p = 0; p < 8; p++) {
            float4 pv;
            pv.x = __expf(sv[p].x - mxv[p]) * riv[p];
            pv.y = __expf(sv[p].y - mxv[p]) * riv[p];
            pv.z = __expf(sv[p].z - mxv[p]) * riv[p];
            pv.w = __expf(sv[p].w - mxv[p]) * riv[p];
            *(float4*)&attn[abase + (size_t)(q0 + lr + 16 * p) * Sq + kt * 64 + c4] = pv;
            uint2 h, l; split4(pv, h, l);
            uint32_t off = SW128((lr + 16 * p) * 128 + c4 * 2);
            *(uint2*)(Ph + off) = h; *(uint2*)(Pl + off) = l;
        }
        #pragma unroll
        for (int p = 0; p < 4; p++) {
            uint2 h, l; split4(vv[p], h, l);
            uint32_t off = SW128((lr + 16 * p) * 128 + c4 * 2);
            *(uint2*)(Vh + off) = h; *(uint2*)(Vl + off) = l;
        }
        __syncthreads();
        if (kt < 31) {
            #pragma unroll
            for (int p = 0; p < 8; p++)
                sv[p] = *(const float4*)&attn[abase + (size_t)(q0 + lr + 16 * p) * Sq + (kt + 1) * 64 + c4];
            #pragma unroll
            for (int p = 0; p < 4; p++)
                vv[p] = *(const float4*)&g_V[vbase + (size_t)((kt + 1) * 64 + lr + 16 * p) * 64 + c4];
        }
        uint32_t sPh = sBase + buf * 49152, sPl = sPh + 16384;
        uint32_t sVh = sPl + 16384, sVl = sVh + 8192;
        #pragma unroll
        for (int ks = 0; ks < 4; ks++) {
            uint32_t bhf[4][2], blf[4][2];
            #pragma unroll
            for (int in = 0; in < 4; in++) {
                int krow = ks * 16 + (lane & 15);
                int nb = (wn * 32 + in * 8) * 2;
                uint32_t off = SW128(krow * 128 + nb);
                ldsm2t(bhf[in][0], bhf[in][1], sVh + off);
                ldsm2t(blf[in][0], blf[in][1], sVl + off);
            }
            #pragma unroll
            for (int im = 0; im < 2; im++) {
                int arow = wm * 32 + im * 16 + (lane & 15);
                int acb = (ks * 16 + ((lane >> 4) << 3)) * 2;
                uint32_t off = SW128(arow * 128 + acb);
                uint32_t ah[4], al[4];
                ldsm4(ah[0], ah[1], ah[2], ah[3], sPh + off);
                ldsm4(al[0], al[1], al[2], al[3], sPl + off);
                #pragma unroll
                for (int in = 0; in < 4; in++) {
                    mmab(acc[im][in], ah, bhf[in]);
                    mmab(acc[im][in], al, bhf[in]);
                    mmab(acc[im][in], ah, blf[in]);
                }
            }
        }
    }

    int b = bh >> 4, h = bh & 15;
    int g = lane >> 2, c2 = (lane & 3) * 2;
    #pragma unroll
    for (int im = 0; im < 2; im++)
        #pragma unroll
        for (int in = 0; in < 4; in++)
            #pragma unroll
            for (int hh = 0; hh < 2; hh++) {
                int q = q0 + wm * 32 + im * 16 + g + hh * 8;
                int n = wn * 32 + in * 8 + c2;
                float2 v = make_float2(acc[im][in][hh * 2], acc[im][in][hh * 2 + 1]);
                *(float2*)&g_ctx[(size_t)(b * Sq + q) * 1024 + h * 64 + n] = v;
            }
}

// ---------------- residual + LayerNorm ----------------
__global__ void __launch_bounds__(256) ln_kernel(const float* __restrict__ inQ,
                                                 const float* __restrict__ gamma,
                                                 const float* __restrict__ beta,
                                                 float* __restrict__ out) {
    int m = blockIdx.x, t = threadIdx.x;
    size_t base = (size_t)m * 1024;
    float x[4];
    float s = 0.0f;
    #pragma unroll
    for (int i = 0; i < 4; i++) {
        int c = i * 256 + t;
        x[i] = g_proj[base + c] + inQ[base + c];
        s += x[i];
    }
    s = block_sum(s);
    float mu = s * (1.0f / 1024.0f);
    float s2 = 0.0f;
    #pragma unroll
    for (int i = 0; i < 4; i++) { float d = x[i] - mu; s2 += d * d; }
    s2 = block_sum(s2);
    float rstd = rsqrtf(s2 * (1.0f / 1024.0f) + 1e-5f);
    #pragma unroll
    for (int i = 0; i < 4; i++) {
        int c = i * 256 + t;
        out[base + c] = (x[i] - mu) * rstd * gamma[c] + beta[c];
    }
}

// ---------------- launch ----------------
extern "C" void kernel_launch(void* const* d_in, const int* in_sizes, int n_in,
                              void* d_out, int out_size) {
    const float* inQ = (const float*)d_in[0];
    const float* inK = (const float*)d_in[1];
    const float* inV = (const float*)d_in[2];
    const unsigned char* mask = (const unsigned char*)d_in[3];
    const float* wQ = (const float*)d_in[4];
    const float* wK = (const float*)d_in[5];
    const float* wV = (const float*)d_in[6];
    const float* wO = (const float*)d_in[7];
    const float* gamma = (const float*)d_in[8];
    const float* beta = (const float*)d_in[9];
    float* out = (float*)d_out;
    float* attn = out + (size_t)Bq * Sq * Eq;

    const int GEMM_SMEM = 131072;  // 2 x 64KB
    const int SC_SMEM   = 65536;
    const int AV_SMEM   = 98304;   // 2 x 48KB
    cudaFuncSetAttribute(gemm8192, cudaFuncAttributeMaxDynamicSharedMemorySize, GEMM_SMEM);
    cudaFuncSetAttribute(scores_kernel, cudaFuncAttributeMaxDynamicSharedMemorySize, SC_SMEM);
    cudaFuncSetAttribute(av_kernel, cudaFuncAttributeMaxDynamicSharedMemorySize, AV_SMEM);

    dim3 blk(256);
    gemm8192<<<dim3(8, 64), blk, GEMM_SMEM>>>(inQ, wQ, 0);
    gemm8192<<<dim3(8, 64), blk, GEMM_SMEM>>>(inK, wK, 1);
    gemm8192<<<dim3(8, 64), blk, GEMM_SMEM>>>(inV, wV, 2);
    scores_kernel<<<dim3(16, 16, 64), blk, SC_SMEM>>>(mask, attn);
    reduce_stats<<<Bq * Hq * Sq / 8, blk>>>();
    av_kernel<<<dim3(16, 64), blk, AV_SMEM>>>(attn);
    gemm8192<<<dim3(8, 64), blk, GEMM_SMEM>>>(nullptr, wO, 3);
    ln_kernel<<<Bq * Sq, blk>>>(inQ, gamma, beta, out);
}